// round 16
// baseline (speedup 1.0000x reference)
#include <cuda_runtime.h>

#define B_ 64
#define T_ 800
#define J_ 50
#define D_ 200

constexpr int TPB  = 256;
constexpr int TBLK = 64;         // t-rows per block
constexpr int NBLK = 13;         // ceil(800/64)
constexpr int UP   = 204;        // u_s pitch (floats); conflict-free B reads
constexpr int UP4  = 51;
constexpr int UROWS = 52;        // 50 u rows + w_h row (50) + zero row (51)
constexpr int AP   = 68;         // a_s pitch (floats); conflict-free A reads
constexpr int JP   = 64;         // padded J
constexpr int STP  = 36;         // stage pitch; conflict-free A reads
constexpr int STG  = 64 * STP;   // one stage buffer (floats) = 2304
constexpr int NSTG = 3;          // slots (issue-ahead 2, wait_group 1)
constexpr int STG_OFF = UROWS * UP;   // 10608 floats

// scratch (no cudaMalloc allowed)
__device__ float2 g_cm[B_ * NBLK];
__device__ float  g_part[B_ * NBLK * D_];
__device__ __align__(16) float g_q2c[B_ * D_];

__device__ __forceinline__ float warpSum(float v) {
    #pragma unroll
    for (int o = 16; o > 0; o >>= 1) v += __shfl_xor_sync(0xffffffffu, v, o);
    return v;
}
__device__ __forceinline__ float warpMax(float v) {
    #pragma unroll
    for (int o = 16; o > 0; o >>= 1) v = fmaxf(v, __shfl_xor_sync(0xffffffffu, v, o));
    return v;
}
__device__ __forceinline__ void mma8(float d[4], const unsigned a[4], const unsigned b[2]) {
    asm("mma.sync.aligned.m16n8k8.row.col.f32.tf32.tf32.f32 "
        "{%0,%1,%2,%3}, {%4,%5,%6,%7}, {%8,%9}, {%0,%1,%2,%3};"
        : "+f"(d[0]), "+f"(d[1]), "+f"(d[2]), "+f"(d[3])
        : "r"(a[0]), "r"(a[1]), "r"(a[2]), "r"(a[3]), "r"(b[0]), "r"(b[1]));
}
__device__ __forceinline__ void split2(float x, unsigned& hi, unsigned& lo) {
    unsigned hh = __float_as_uint(x) & 0xffffe000u;
    hi = hh;
    lo = __float_as_uint(x - __uint_as_float(hh));
}

// c2q chunk: NTN n-tiles starting at ntBeg; result scaled by 1/w_hu[d]
template<int NTN>
__device__ __forceinline__ void c2q_chunk(
    int ntBeg, int dbase, const float* a_s, const float* u_s, const float* rwhu_s,
    int strip, int g, int tg,
    const float* hp0, const float* hp1, bool v0, bool v1,
    float* o0, float* o1)
{
    float dacc[NTN][4];
    #pragma unroll
    for (int q = 0; q < NTN; q++) {
        dacc[q][0] = 0.f; dacc[q][1] = 0.f; dacc[q][2] = 0.f; dacc[q][3] = 0.f;
    }
    const float* aR0 = a_s + (strip * 16 + g) * AP;
    const float* aR1 = aR0 + 8 * AP;
    #pragma unroll
    for (int ks = 0; ks < 8; ks++) {
        const int k0 = ks * 8 + tg;
        const int r0 = (k0 <= 51) ? k0 : 51;           // zero row (a cols >=51 are 0)
        const int r1 = (k0 + 4 <= 51) ? (k0 + 4) : 51;
        unsigned ah[4], al[4];
        split2(aR0[k0],     ah[0], al[0]);
        split2(aR1[k0],     ah[1], al[1]);
        split2(aR0[k0 + 4], ah[2], al[2]);
        split2(aR1[k0 + 4], ah[3], al[3]);
        const float* uk0 = u_s + r0 * UP + g;
        const float* uk1 = u_s + r1 * UP + g;
        #pragma unroll
        for (int q = 0; q < NTN; q++) {
            const int nb = dbase + (ntBeg + q) * 8;
            unsigned bh[2], bl[2];
            split2(uk0[nb], bh[0], bl[0]);
            split2(uk1[nb], bh[1], bl[1]);
            mma8(dacc[q], ah, bh);
            mma8(dacc[q], al, bh);
            mma8(dacc[q], ah, bl);
        }
    }
    #pragma unroll
    for (int q = 0; q < NTN; q++) {
        const int cc = dbase + (ntBeg + q) * 8 + 2 * tg;
        const float wx = rwhu_s[cc], wy = rwhu_s[cc + 1];
        if (v0) {
            float2 hv = *(const float2*)&hp0[cc];
            float2 c2 = make_float2(dacc[q][0] * wx, dacc[q][1] * wy);
            __stcs((float2*)(o0 + cc), hv);
            __stcs((float2*)(o0 + 200 + cc), c2);
            __stcs((float2*)(o0 + 400 + cc), make_float2(hv.x * c2.x, hv.y * c2.y));
        }
        if (v1) {
            float2 hv = *(const float2*)&hp1[cc];
            float2 c2 = make_float2(dacc[q][2] * wx, dacc[q][3] * wy);
            __stcs((float2*)(o1 + cc), hv);
            __stcs((float2*)(o1 + 200 + cc), c2);
            __stcs((float2*)(o1 + 400 + cc), make_float2(hv.x * c2.x, hv.y * c2.y));
        }
    }
}

// =====================================================================
// K1 (3xTF32, single-sync 3-slot cp.async pipeline, su from smem u')
// smem: u' 42432 + 3*9216 stage + su/rwhu/m/es 1568 = 71648 B -> 3 CTA/SM
// =====================================================================
__global__ __launch_bounds__(TPB, 3) void bidaf_k1(
    const float* __restrict__ h, const float* __restrict__ u,
    const float* __restrict__ w_h, const float* __restrict__ b_h,
    const float* __restrict__ w_u, const float* __restrict__ b_u,
    const float* __restrict__ w_hu, const float* __restrict__ b_hu,
    float* __restrict__ out)
{
    extern __shared__ float sm[];
    float* u_s    = sm;                         // 52*204
    float* a_s    = sm + STG_OFF;               // 64*68, overlays stage after s-GEMM
    float* su_s   = sm + STG_OFF + NSTG * STG;  // 64
    float* rwhu_s = su_s + JP;                  // 200
    float* m_s    = rwhu_s + D_;                // 64
    float* es_s   = m_s + JP;                   // 64

    const int b = blockIdx.y, c = blockIdx.x, t0 = c * TBLK;
    const int tid = threadIdx.x, warp = tid >> 5, lane = tid & 31;
    const int g = lane >> 2, tg = lane & 3;
    const int strip = warp & 3;     // m16 strip
    const int nh = warp >> 2;       // n-half

    const float4* u4g   = (const float4*)u;
    const float4* h4g   = (const float4*)h;
    const float4* whu4g = (const float4*)w_hu;
    const float4* wh4g  = (const float4*)w_h;
    float4* us4 = (float4*)u_s;
    const float* hb = h + (long)b * T_ * D_;
    const long hb4 = (long)b * T_ * 50;

    // ---- staging thread geometry ----
    const int srow = tid >> 3, sc = tid & 7;
    int tc0 = t0 + srow;      if (tc0 > T_ - 1) tc0 = T_ - 1;
    int tc1 = t0 + srow + 32; if (tc1 > T_ - 1) tc1 = T_ - 1;
    const unsigned sbase = (unsigned)__cvta_generic_to_shared(sm + STG_OFF);

    // ---- kick off rounds 0,1 (slots 0,1); issue-ahead depth 2 ----
    #pragma unroll
    for (int rd = 0; rd < 2; rd++) {
        const float4* s0 = h4g + hb4 + (long)tc0 * 50 + rd * 8 + sc;
        const float4* s1 = h4g + hb4 + (long)tc1 * 50 + rd * 8 + sc;
        unsigned d0 = sbase + (unsigned)(rd * STG + srow * STP + sc * 4) * 4u;
        unsigned d1 = d0 + 32u * STP * 4u;
        asm volatile("cp.async.ca.shared.global [%0], [%1], 16;" :: "r"(d0), "l"(s0));
        asm volatile("cp.async.ca.shared.global [%0], [%1], 16;" :: "r"(d1), "l"(s1));
        asm volatile("cp.async.commit_group;" ::: "memory");
    }

    // ---- u' tile: u'[j][d] = u[j][d]*w_hu[d]; row 50 = w_h; row 51 = 0 ----
    for (int idx = tid; idx < UROWS * UP4; idx += TPB) {
        int j = idx / UP4, k = idx - j * UP4;
        if (k < 50) {
            float4 v;
            if (j < J_) {
                float4 uv = u4g[(b * J_ + j) * 50 + k];
                float4 wv = whu4g[k];
                v = make_float4(uv.x * wv.x, uv.y * wv.y, uv.z * wv.z, uv.w * wv.w);
            } else if (j == 50) {
                v = wh4g[k];
            } else {
                v = make_float4(0.f, 0.f, 0.f, 0.f);
            }
            us4[j * UP4 + k] = v;
        }
    }
    if (tid < D_) {
        float w = w_hu[tid];
        rwhu_s[tid] = (w != 0.f) ? (1.0f / w) : 0.f;
    }
    const float bias = b_h[0] + b_u[0] + b_hu[0];
    __syncthreads();   // u' + rwhu visible

    // ---- su_s[j] from smem u': su[j] = sum_d u'[j,d]*(w_u[d]*rwhu[d]) ----
    const float4* wu4 = (const float4*)w_u;
    const float4* rw4 = (const float4*)rwhu_s;
    for (int j = warp; j < JP; j += 8) {
        if (j < J_) {
            const float4* ur = us4 + j * UP4;
            float4 a1 = ur[lane], w1 = wu4[lane], r1 = rw4[lane];
            float acc = a1.x * w1.x * r1.x + a1.y * w1.y * r1.y
                      + a1.z * w1.z * r1.z + a1.w * w1.w * r1.w;
            if (lane < 18) {
                float4 a2 = ur[32 + lane], w2 = wu4[32 + lane], r2 = rw4[32 + lane];
                acc += a2.x * w2.x * r2.x + a2.y * w2.y * r2.y
                     + a2.z * w2.z * r2.z + a2.w * w2.w * r2.w;
            }
            acc = warpSum(acc);
            if (lane == 0) su_s[j] = acc + bias;
        } else if (lane == 0) su_s[j] = 0.f;
    }

    // ---- s-GEMM: A = raw h (cp.async, 3 slots, 1 sync/round), B = u' ----
    float accS[4][4];
    #pragma unroll
    for (int nt = 0; nt < 4; nt++) {
        accS[nt][0] = 0.f; accS[nt][1] = 0.f; accS[nt][2] = 0.f; accS[nt][3] = 0.f;
    }
    const float* urp[4];
    #pragma unroll
    for (int nt = 0; nt < 4; nt++) {
        int br = nh * 32 + nt * 8 + g;
        if (br > 51) br = 51;          // zero row
        urp[nt] = u_s + br * UP;
    }
    const float* stA = sm + STG_OFF + (strip * 16 + g) * STP;

    #pragma unroll 1
    for (int rd = 0; rd < 7; rd++) {
        asm volatile("cp.async.wait_group 1;" ::: "memory");  // round rd landed
        __syncthreads();   // publish rd; all warps done consuming rd-1
        if (rd + 2 < 7) {
            const int rn = rd + 2, slot = rn % NSTG;   // slot of rd-1, now free
            const int nf4 = (rn < 6) ? 8 : 2;
            if (sc < nf4) {
                const float4* s0 = h4g + hb4 + (long)tc0 * 50 + rn * 8 + sc;
                const float4* s1 = h4g + hb4 + (long)tc1 * 50 + rn * 8 + sc;
                unsigned d0 = sbase + (unsigned)(slot * STG + srow * STP + sc * 4) * 4u;
                unsigned d1 = d0 + 32u * STP * 4u;
                asm volatile("cp.async.ca.shared.global [%0], [%1], 16;" :: "r"(d0), "l"(s0));
                asm volatile("cp.async.ca.shared.global [%0], [%1], 16;" :: "r"(d1), "l"(s1));
            }
        }
        asm volatile("cp.async.commit_group;" ::: "memory");
        const float* s0r = stA + (rd % NSTG) * STG;
        const float* s1r = s0r + 8 * STP;
        const int nks = (rd < 6) ? 4 : 1;
        for (int ksl = 0; ksl < nks; ksl++) {
            const int c0 = ksl * 8 + tg, c1 = c0 + 4;
            const int kd0 = rd * 32 + c0, kd1 = rd * 32 + c1;
            unsigned ah[4], al[4];
            split2(s0r[c0], ah[0], al[0]);
            split2(s1r[c0], ah[1], al[1]);
            split2(s0r[c1], ah[2], al[2]);
            split2(s1r[c1], ah[3], al[3]);
            #pragma unroll
            for (int nt = 0; nt < 4; nt++) {
                const float* ur = urp[nt];
                unsigned bh[2], bl[2];
                split2(ur[kd0], bh[0], bl[0]);
                split2(ur[kd1], bh[1], bl[1]);
                mma8(accS[nt], ah, bh);
                mma8(accS[nt], al, bh);
                mma8(accS[nt], ah, bl);
            }
        }
    }
    __syncthreads();   // all consumption done; stage region becomes a_s

    // ---- s-GEMM epilogue: s' = acc + su (col 50 = sh; su[>=50]=0) ----
    {
        float* sr0 = a_s + (strip * 16 + g) * AP;
        float* sr1 = sr0 + 8 * AP;
        #pragma unroll
        for (int nt = 0; nt < 4; nt++) {
            const int cc = nh * 32 + nt * 8 + 2 * tg;
            float2 su2 = *(const float2*)&su_s[cc];
            *(float2*)&sr0[cc] = make_float2(accS[nt][0] + su2.x, accS[nt][1] + su2.y);
            *(float2*)&sr1[cc] = make_float2(accS[nt][2] + su2.x, accS[nt][3] + su2.y);
        }
    }
    __syncthreads();

    // ---- softmax: 4 threads/row; col 50 = sh, cols >=50 masked to 0 ----
    {
        const int row = tid >> 2, q = tid & 3;
        float4* ar = (float4*)&a_s[row * AP + q * 16];
        float4 v0 = ar[0], v1 = ar[1], v2 = ar[2], v3 = ar[3];
        float shv;
        if (q == 3) {
            shv = v0.z;                        // col 50
            v0.z = -1e30f; v0.w = -1e30f;
            v1 = make_float4(-1e30f, -1e30f, -1e30f, -1e30f);
            v2 = v1; v3 = v1;
        } else {
            shv = a_s[row * AP + 50];
        }
        float mx = fmaxf(fmaxf(fmaxf(v0.x, v0.y), fmaxf(v0.z, v0.w)),
                   fmaxf(fmaxf(fmaxf(v1.x, v1.y), fmaxf(v1.z, v1.w)),
                   fmaxf(fmaxf(fmaxf(v2.x, v2.y), fmaxf(v2.z, v2.w)),
                         fmaxf(fmaxf(v3.x, v3.y), fmaxf(v3.z, v3.w)))));
        mx = fmaxf(mx, __shfl_xor_sync(0xffffffffu, mx, 1));
        mx = fmaxf(mx, __shfl_xor_sync(0xffffffffu, mx, 2));
        v0.x = __expf(v0.x - mx); v0.y = __expf(v0.y - mx);
        v0.z = __expf(v0.z - mx); v0.w = __expf(v0.w - mx);
        v1.x = __expf(v1.x - mx); v1.y = __expf(v1.y - mx);
        v1.z = __expf(v1.z - mx); v1.w = __expf(v1.w - mx);
        v2.x = __expf(v2.x - mx); v2.y = __expf(v2.y - mx);
        v2.z = __expf(v2.z - mx); v2.w = __expf(v2.w - mx);
        v3.x = __expf(v3.x - mx); v3.y = __expf(v3.y - mx);
        v3.z = __expf(v3.z - mx); v3.w = __expf(v3.w - mx);
        float s = (v0.x + v0.y + v0.z + v0.w) + (v1.x + v1.y + v1.z + v1.w)
                + (v2.x + v2.y + v2.z + v2.w) + (v3.x + v3.y + v3.z + v3.w);
        s += __shfl_xor_sync(0xffffffffu, s, 1);
        s += __shfl_xor_sync(0xffffffffu, s, 2);
        const float inv = 1.f / s;
        v0.x *= inv; v0.y *= inv; v0.z *= inv; v0.w *= inv;
        v1.x *= inv; v1.y *= inv; v1.z *= inv; v1.w *= inv;
        v2.x *= inv; v2.y *= inv; v2.z *= inv; v2.w *= inv;
        v3.x *= inv; v3.y *= inv; v3.z *= inv; v3.w *= inv;
        ar[0] = v0; ar[1] = v1; ar[2] = v2; ar[3] = v3;   // masked cols -> 0
        if (q == 0) m_s[row] = (t0 + row < T_) ? (mx + shv) : -3.0e38f;
    }
    __syncthreads();

    // ---- warp 0: chunk max/expsum over 64 rows ----
    if (warp == 0) {
        float m0 = m_s[lane], m1 = m_s[lane + 32];
        float mc = warpMax(fmaxf(m0, m1));
        float e0 = __expf(m0 - mc), e1 = __expf(m1 - mc);
        float sc2 = warpSum(e0 + e1);
        es_s[lane] = e0; es_s[lane + 32] = e1;
        if (lane == 0) g_cm[b * NBLK + c] = make_float2(mc, sc2);
    }

    // ---- c2q GEMM + fused epilogue (result scaled by 1/w_hu) ----
    {
        const int dbase = nh * 104;      // half0: 13 tiles, half1: 12 tiles
        const int tr0 = t0 + strip * 16 + g, tr1 = tr0 + 8;
        const bool v0 = tr0 < T_, v1 = tr1 < T_;
        const float* hp0 = hb + (long)(v0 ? tr0 : 0) * D_;
        const float* hp1 = hb + (long)(v1 ? tr1 : 0) * D_;
        float* o0 = out + (long)(b * T_ + (v0 ? tr0 : 0)) * (4 * D_);
        float* o1 = out + (long)(b * T_ + (v1 ? tr1 : 0)) * (4 * D_);
        if (nh == 0) {
            c2q_chunk<7>(0, dbase, a_s, u_s, rwhu_s, strip, g, tg, hp0, hp1, v0, v1, o0, o1);
            c2q_chunk<6>(7, dbase, a_s, u_s, rwhu_s, strip, g, tg, hp0, hp1, v0, v1, o0, o1);
        } else {
            c2q_chunk<7>(0, dbase, a_s, u_s, rwhu_s, strip, g, tg, hp0, hp1, v0, v1, o0, o1);
            c2q_chunk<5>(7, dbase, a_s, u_s, rwhu_s, strip, g, tg, hp0, hp1, v0, v1, o0, o1);
        }
    }

    // ---- chunk-local q2c partial ----
    __syncthreads();
    if (tid < D_) {
        const int RV = (T_ - t0 < TBLK) ? (T_ - t0) : TBLK;
        const float* hp = hb + (long)t0 * D_ + tid;
        float a0 = 0.f, a1 = 0.f, a2 = 0.f, a3 = 0.f;
        for (int r = 0; r < RV; r += 4) {
            a0 += es_s[r]     * hp[r * D_];
            a1 += es_s[r + 1] * hp[(r + 1) * D_];
            a2 += es_s[r + 2] * hp[(r + 2) * D_];
            a3 += es_s[r + 3] * hp[(r + 3) * D_];
        }
        g_part[(b * NBLK + c) * D_ + tid] = (a0 + a1) + (a2 + a3);
    }
}

// =====================================================================
// K2: per-batch combine -> g_q2c
// =====================================================================
__global__ __launch_bounds__(256) void bidaf_k2()
{
    __shared__ float ws[32];
    __shared__ float Ss;
    const int b = blockIdx.x, tid = threadIdx.x;
    if (tid < 32) {
        float2 cm = (tid < NBLK) ? g_cm[b * NBLK + tid] : make_float2(-3.0e38f, 0.f);
        float M = warpMax(cm.x);
        float e = (tid < NBLK) ? __expf(cm.x - M) : 0.f;
        float S = warpSum(e * cm.y);
        ws[tid] = e;
        if (tid == 0) Ss = S;
    }
    __syncthreads();
    if (tid < D_) {
        float acc = 0.f;
        #pragma unroll
        for (int c2 = 0; c2 < NBLK; c2++)
            acc += ws[c2] * g_part[(b * NBLK + c2) * D_ + tid];
        g_q2c[b * D_ + tid] = acc / Ss;
    }
}

// =====================================================================
// K3: out[b,t,600:800] = h * q2c
// =====================================================================
__global__ __launch_bounds__(256) void bidaf_k3(const float* __restrict__ h,
                                                float* __restrict__ out)
{
    long idx = (long)blockIdx.x * 256 + threadIdx.x;   // float4 index
    if (idx >= (long)B_ * T_ * 50) return;
    int d4 = (int)(idx % 50);
    long bt = idx / 50;
    int b = (int)(bt / T_);
    float4 hv = __ldg(((const float4*)h) + idx);
    float4 q  = __ldg(((const float4*)g_q2c) + b * 50 + d4);
    __stcs(((float4*)out) + bt * 200 + 150 + d4,
           make_float4(hv.x * q.x, hv.y * q.y, hv.z * q.z, hv.w * q.w));
}

// =====================================================================
extern "C" void kernel_launch(void* const* d_in, const int* in_sizes, int n_in,
                              void* d_out, int out_size)
{
    const float* h    = (const float*)d_in[0];
    const float* u    = (const float*)d_in[1];
    const float* w_h  = (const float*)d_in[2];
    const float* b_h  = (const float*)d_in[3];
    const float* w_u  = (const float*)d_in[4];
    const float* b_u  = (const float*)d_in[5];
    const float* w_hu = (const float*)d_in[6];
    const float* b_hu = (const float*)d_in[7];
    float* out = (float*)d_out;

    // u' + 3 stage buffers + su + rwhu + m + es
    constexpr int SMEM1 = (STG_OFF + NSTG * STG + JP + D_ + JP + JP) * 4;  // 71648
    cudaFuncSetAttribute(bidaf_k1, cudaFuncAttributeMaxDynamicSharedMemorySize, SMEM1);

    bidaf_k1<<<dim3(NBLK, B_), TPB, SMEM1>>>(h, u, w_h, b_h, w_u, b_u, w_hu, b_hu, out);
    bidaf_k2<<<B_, 256>>>();
    int total4 = B_ * T_ * 50;
    bidaf_k3<<<(total4 + 255) / 256, 256>>>(h, out);
}

// round 17
// speedup vs baseline: 1.1029x; 1.1029x over previous
#include <cuda_runtime.h>

#define B_ 64
#define T_ 800
#define J_ 50
#define D_ 200

constexpr int TPB  = 256;
constexpr int TBLK = 64;         // t-rows per block
constexpr int NBLK = 13;         // ceil(800/64)
constexpr int UP   = 204;        // u_s pitch (floats); conflict-free B reads
constexpr int UP4  = 51;
constexpr int UROWS = 52;        // 50 u rows + w_h row (50) + zero row (51)
constexpr int AP   = 68;         // a_s pitch (floats); conflict-free A reads
constexpr int JP   = 64;         // padded J
constexpr int STP  = 36;         // stage pitch; conflict-free A reads
constexpr int STG  = 64 * STP;   // one stage buffer (floats) = 2304
constexpr int STG_OFF = UROWS * UP;   // 10608 floats

// scratch (no cudaMalloc allowed)
__device__ float2 g_cm[B_ * NBLK];
__device__ float  g_part[B_ * NBLK * D_];
__device__ __align__(16) float g_q2c[B_ * D_];

__device__ __forceinline__ float warpSum(float v) {
    #pragma unroll
    for (int o = 16; o > 0; o >>= 1) v += __shfl_xor_sync(0xffffffffu, v, o);
    return v;
}
__device__ __forceinline__ float warpMax(float v) {
    #pragma unroll
    for (int o = 16; o > 0; o >>= 1) v = fmaxf(v, __shfl_xor_sync(0xffffffffu, v, o));
    return v;
}
__device__ __forceinline__ void mma8(float d[4], const unsigned a[4], const unsigned b[2]) {
    asm("mma.sync.aligned.m16n8k8.row.col.f32.tf32.tf32.f32 "
        "{%0,%1,%2,%3}, {%4,%5,%6,%7}, {%8,%9}, {%0,%1,%2,%3};"
        : "+f"(d[0]), "+f"(d[1]), "+f"(d[2]), "+f"(d[3])
        : "r"(a[0]), "r"(a[1]), "r"(a[2]), "r"(a[3]), "r"(b[0]), "r"(b[1]));
}
__device__ __forceinline__ void split2(float x, unsigned& hi, unsigned& lo) {
    unsigned hh = __float_as_uint(x) & 0xffffe000u;
    hi = hh;
    lo = __float_as_uint(x - __uint_as_float(hh));
}
// round-to-nearest tf32 (done once at tile load)
__device__ __forceinline__ float tf32r(float x) {
    float y;
    asm("cvt.rna.tf32.f32 %0, %1;" : "=f"(y) : "f"(x));
    return y;
}

// c2q chunk: NTN n-tiles starting at ntBeg; A split hi/lo, B = pre-tf32 u'
template<int NTN>
__device__ __forceinline__ void c2q_chunk(
    int ntBeg, int dbase, const float* a_s, const float* u_s, const float* rwhu_s,
    int strip, int g, int tg,
    const float* hp0, const float* hp1, bool v0, bool v1,
    float* o0, float* o1)
{
    float dacc[NTN][4];
    #pragma unroll
    for (int q = 0; q < NTN; q++) {
        dacc[q][0] = 0.f; dacc[q][1] = 0.f; dacc[q][2] = 0.f; dacc[q][3] = 0.f;
    }
    const float* aR0 = a_s + (strip * 16 + g) * AP;
    const float* aR1 = aR0 + 8 * AP;
    #pragma unroll
    for (int ks = 0; ks < 8; ks++) {
        const int k0 = ks * 8 + tg;
        const int r0 = (k0 <= 51) ? k0 : 51;           // zero row (a cols >=51 are 0)
        const int r1 = (k0 + 4 <= 51) ? (k0 + 4) : 51;
        unsigned ah[4], al[4];
        split2(aR0[k0],     ah[0], al[0]);
        split2(aR1[k0],     ah[1], al[1]);
        split2(aR0[k0 + 4], ah[2], al[2]);
        split2(aR1[k0 + 4], ah[3], al[3]);
        const float* uk0 = u_s + r0 * UP + g;
        const float* uk1 = u_s + r1 * UP + g;
        #pragma unroll
        for (int q = 0; q < NTN; q++) {
            const int nb = dbase + (ntBeg + q) * 8;
            unsigned bb[2];
            bb[0] = __float_as_uint(uk0[nb]);
            bb[1] = __float_as_uint(uk1[nb]);
            mma8(dacc[q], ah, bb);
            mma8(dacc[q], al, bb);
        }
    }
    #pragma unroll
    for (int q = 0; q < NTN; q++) {
        const int cc = dbase + (ntBeg + q) * 8 + 2 * tg;
        const float wx = rwhu_s[cc], wy = rwhu_s[cc + 1];
        if (v0) {
            float2 hv = *(const float2*)&hp0[cc];
            float2 c2 = make_float2(dacc[q][0] * wx, dacc[q][1] * wy);
            __stcs((float2*)(o0 + cc), hv);
            __stcs((float2*)(o0 + 200 + cc), c2);
            __stcs((float2*)(o0 + 400 + cc), make_float2(hv.x * c2.x, hv.y * c2.y));
        }
        if (v1) {
            float2 hv = *(const float2*)&hp1[cc];
            float2 c2 = make_float2(dacc[q][2] * wx, dacc[q][3] * wy);
            __stcs((float2*)(o1 + cc), hv);
            __stcs((float2*)(o1 + 200 + cc), c2);
            __stcs((float2*)(o1 + 400 + cc), make_float2(hv.x * c2.x, hv.y * c2.y));
        }
    }
}

// =====================================================================
// K1 (2xTF32: exact-A x tf32-rounded-B, cp.async-pipelined A)
// smem: u' 42432 + stage 2*9216 + su/rwhu/m/es 1568 = 62432 B -> 3 CTA/SM
// =====================================================================
__global__ __launch_bounds__(TPB, 3) void bidaf_k1(
    const float* __restrict__ h, const float* __restrict__ u,
    const float* __restrict__ w_h, const float* __restrict__ b_h,
    const float* __restrict__ w_u, const float* __restrict__ b_u,
    const float* __restrict__ w_hu, const float* __restrict__ b_hu,
    float* __restrict__ out)
{
    extern __shared__ float sm[];
    float* u_s    = sm;                      // 52*204
    float* a_s    = sm + STG_OFF;            // 64*68, overlays stage after s-GEMM
    float* su_s   = sm + STG_OFF + 2 * STG;  // 64
    float* rwhu_s = su_s + JP;               // 200
    float* m_s    = rwhu_s + D_;             // 64
    float* es_s   = m_s + JP;                // 64

    const int b = blockIdx.y, c = blockIdx.x, t0 = c * TBLK;
    const int tid = threadIdx.x, warp = tid >> 5, lane = tid & 31;
    const int g = lane >> 2, tg = lane & 3;
    const int strip = warp & 3;     // m16 strip
    const int nh = warp >> 2;       // n-half

    const float4* u4g   = (const float4*)u;
    const float4* h4g   = (const float4*)h;
    const float4* whu4g = (const float4*)w_hu;
    const float4* wh4g  = (const float4*)w_h;
    float4* us4 = (float4*)u_s;
    const float* hb = h + (long)b * T_ * D_;
    const long hb4 = (long)b * T_ * 50;

    // ---- staging thread geometry ----
    const int srow = tid >> 3, sc = tid & 7;
    int tc0 = t0 + srow;      if (tc0 > T_ - 1) tc0 = T_ - 1;
    int tc1 = t0 + srow + 32; if (tc1 > T_ - 1) tc1 = T_ - 1;
    const unsigned sbase = (unsigned)__cvta_generic_to_shared(sm + STG_OFF);

    // ---- kick off rounds 0,1 immediately ----
    #pragma unroll
    for (int rd = 0; rd < 2; rd++) {
        if (sc < 8) {
            const float4* s0 = h4g + hb4 + (long)tc0 * 50 + rd * 8 + sc;
            const float4* s1 = h4g + hb4 + (long)tc1 * 50 + rd * 8 + sc;
            unsigned d0 = sbase + (unsigned)(rd * STG + srow * STP + sc * 4) * 4u;
            unsigned d1 = d0 + 32u * STP * 4u;
            asm volatile("cp.async.ca.shared.global [%0], [%1], 16;" :: "r"(d0), "l"(s0));
            asm volatile("cp.async.ca.shared.global [%0], [%1], 16;" :: "r"(d1), "l"(s1));
        }
        asm volatile("cp.async.commit_group;" ::: "memory");
    }

    // ---- u' tile: u'[j][d] = tf32(u[j][d]*w_hu[d]); row 50 = tf32(w_h); row 51 = 0 ----
    for (int idx = tid; idx < UROWS * UP4; idx += TPB) {
        int j = idx / UP4, k = idx - j * UP4;
        if (k < 50) {
            float4 v;
            if (j < J_) {
                float4 uv = u4g[(b * J_ + j) * 50 + k];
                float4 wv = whu4g[k];
                v = make_float4(tf32r(uv.x * wv.x), tf32r(uv.y * wv.y),
                                tf32r(uv.z * wv.z), tf32r(uv.w * wv.w));
            } else if (j == 50) {
                float4 wv = wh4g[k];
                v = make_float4(tf32r(wv.x), tf32r(wv.y), tf32r(wv.z), tf32r(wv.w));
            } else {
                v = make_float4(0.f, 0.f, 0.f, 0.f);
            }
            us4[j * UP4 + k] = v;
        }
    }
    if (tid < D_) {
        float w = w_hu[tid];
        rwhu_s[tid] = (w != 0.f) ? (1.0f / w) : 0.f;
    }
    const float bias = b_h[0] + b_u[0] + b_hu[0];

    // ---- su_s[j] from GLOBAL u (exact); su[>=50] = 0 ----
    const float4* wu4 = (const float4*)w_u;
    for (int j = warp; j < JP; j += 8) {
        if (j < J_) {
            const float4* ug = u4g + (long)(b * J_ + j) * 50;
            float4 a1 = ug[lane], w1 = wu4[lane];
            float acc = a1.x * w1.x + a1.y * w1.y + a1.z * w1.z + a1.w * w1.w;
            if (lane < 18) {
                float4 a2 = ug[32 + lane], w2 = wu4[32 + lane];
                acc += a2.x * w2.x + a2.y * w2.y + a2.z * w2.z + a2.w * w2.w;
            }
            acc = warpSum(acc);
            if (lane == 0) su_s[j] = acc + bias;
        } else if (lane == 0) su_s[j] = 0.f;
    }
    __syncthreads();   // u', su, rwhu ready

    // ---- s-GEMM: A = raw h (cp.async staged, split hi/lo), B = u' direct ----
    float accS[4][4];
    #pragma unroll
    for (int nt = 0; nt < 4; nt++) {
        accS[nt][0] = 0.f; accS[nt][1] = 0.f; accS[nt][2] = 0.f; accS[nt][3] = 0.f;
    }
    const float* urp[4];
    #pragma unroll
    for (int nt = 0; nt < 4; nt++) {
        int br = nh * 32 + nt * 8 + g;
        if (br > 51) br = 51;          // zero row
        urp[nt] = u_s + br * UP;
    }
    const float* stA = sm + STG_OFF + (strip * 16 + g) * STP;

    #pragma unroll 1
    for (int rd = 0; rd < 7; rd++) {
        asm volatile("cp.async.wait_group 1;" ::: "memory");
        __syncthreads();                        // round rd resident everywhere
        const float* s0r = stA + (rd & 1) * STG;
        const float* s1r = s0r + 8 * STP;
        const int nks = (rd < 6) ? 4 : 1;
        for (int ksl = 0; ksl < nks; ksl++) {
            const int c0 = ksl * 8 + tg, c1 = c0 + 4;
            const int kd0 = rd * 32 + c0, kd1 = rd * 32 + c1;
            unsigned ah[4], al[4];
            split2(s0r[c0], ah[0], al[0]);
            split2(s1r[c0], ah[1], al[1]);
            split2(s0r[c1], ah[2], al[2]);
            split2(s1r[c1], ah[3], al[3]);
            #pragma unroll
            for (int nt = 0; nt < 4; nt++) {
                const float* ur = urp[nt];
                unsigned bb[2];
                bb[0] = __float_as_uint(ur[kd0]);
                bb[1] = __float_as_uint(ur[kd1]);
                mma8(accS[nt], ah, bb);
                mma8(accS[nt], al, bb);
            }
        }
        __syncthreads();                        // buffer rd&1 free
        if (rd + 2 < 7) {
            const int rn = rd + 2;
            const int nf4 = (rn < 6) ? 8 : 2;
            if (sc < nf4) {
                const float4* s0 = h4g + hb4 + (long)tc0 * 50 + rn * 8 + sc;
                const float4* s1 = h4g + hb4 + (long)tc1 * 50 + rn * 8 + sc;
                unsigned d0 = sbase + (unsigned)((rd & 1) * STG + srow * STP + sc * 4) * 4u;
                unsigned d1 = d0 + 32u * STP * 4u;
                asm volatile("cp.async.ca.shared.global [%0], [%1], 16;" :: "r"(d0), "l"(s0));
                asm volatile("cp.async.ca.shared.global [%0], [%1], 16;" :: "r"(d1), "l"(s1));
            }
        }
        asm volatile("cp.async.commit_group;" ::: "memory");   // keep group count
    }

    // ---- s-GEMM epilogue: s' = acc + su (col 50 keeps sh; su[>=50]=0) ----
    {
        float* sr0 = a_s + (strip * 16 + g) * AP;
        float* sr1 = sr0 + 8 * AP;
        #pragma unroll
        for (int nt = 0; nt < 4; nt++) {
            const int cc = nh * 32 + nt * 8 + 2 * tg;
            float2 su2 = *(const float2*)&su_s[cc];
            *(float2*)&sr0[cc] = make_float2(accS[nt][0] + su2.x, accS[nt][1] + su2.y);
            *(float2*)&sr1[cc] = make_float2(accS[nt][2] + su2.x, accS[nt][3] + su2.y);
        }
    }
    __syncthreads();

    // ---- softmax: 4 threads/row; col 50 = sh, cols >=50 masked to 0 ----
    {
        const int row = tid >> 2, q = tid & 3;
        float4* ar = (float4*)&a_s[row * AP + q * 16];
        float4 v0 = ar[0], v1 = ar[1], v2 = ar[2], v3 = ar[3];
        float shv;
        if (q == 3) {
            shv = v0.z;                        // col 50
            v0.z = -1e30f; v0.w = -1e30f;
            v1 = make_float4(-1e30f, -1e30f, -1e30f, -1e30f);
            v2 = v1; v3 = v1;
        } else {
            shv = a_s[row * AP + 50];
        }
        float mx = fmaxf(fmaxf(fmaxf(v0.x, v0.y), fmaxf(v0.z, v0.w)),
                   fmaxf(fmaxf(fmaxf(v1.x, v1.y), fmaxf(v1.z, v1.w)),
                   fmaxf(fmaxf(fmaxf(v2.x, v2.y), fmaxf(v2.z, v2.w)),
                         fmaxf(fmaxf(v3.x, v3.y), fmaxf(v3.z, v3.w)))));
        mx = fmaxf(mx, __shfl_xor_sync(0xffffffffu, mx, 1));
        mx = fmaxf(mx, __shfl_xor_sync(0xffffffffu, mx, 2));
        v0.x = __expf(v0.x - mx); v0.y = __expf(v0.y - mx);
        v0.z = __expf(v0.z - mx); v0.w = __expf(v0.w - mx);
        v1.x = __expf(v1.x - mx); v1.y = __expf(v1.y - mx);
        v1.z = __expf(v1.z - mx); v1.w = __expf(v1.w - mx);
        v2.x = __expf(v2.x - mx); v2.y = __expf(v2.y - mx);
        v2.z = __expf(v2.z - mx); v2.w = __expf(v2.w - mx);
        v3.x = __expf(v3.x - mx); v3.y = __expf(v3.y - mx);
        v3.z = __expf(v3.z - mx); v3.w = __expf(v3.w - mx);
        float s = (v0.x + v0.y + v0.z + v0.w) + (v1.x + v1.y + v1.z + v1.w)
                + (v2.x + v2.y + v2.z + v2.w) + (v3.x + v3.y + v3.z + v3.w);
        s += __shfl_xor_sync(0xffffffffu, s, 1);
        s += __shfl_xor_sync(0xffffffffu, s, 2);
        const float inv = 1.f / s;
        v0.x *= inv; v0.y *= inv; v0.z *= inv; v0.w *= inv;
        v1.x *= inv; v1.y *= inv; v1.z *= inv; v1.w *= inv;
        v2.x *= inv; v2.y *= inv; v2.z *= inv; v2.w *= inv;
        v3.x *= inv; v3.y *= inv; v3.z *= inv; v3.w *= inv;
        ar[0] = v0; ar[1] = v1; ar[2] = v2; ar[3] = v3;   // masked cols -> 0
        if (q == 0) m_s[row] = (t0 + row < T_) ? (mx + shv) : -3.0e38f;
    }
    __syncthreads();

    // ---- warp 0: chunk max/expsum over 64 rows ----
    if (warp == 0) {
        float m0 = m_s[lane], m1 = m_s[lane + 32];
        float mc = warpMax(fmaxf(m0, m1));
        float e0 = __expf(m0 - mc), e1 = __expf(m1 - mc);
        float sc2 = warpSum(e0 + e1);
        es_s[lane] = e0; es_s[lane + 32] = e1;
        if (lane == 0) g_cm[b * NBLK + c] = make_float2(mc, sc2);
    }

    // ---- c2q GEMM + fused epilogue (result scaled by 1/w_hu) ----
    {
        const int dbase = nh * 104;      // half0: 13 tiles, half1: 12 tiles
        const int tr0 = t0 + strip * 16 + g, tr1 = tr0 + 8;
        const bool v0 = tr0 < T_, v1 = tr1 < T_;
        const float* hp0 = hb + (long)(v0 ? tr0 : 0) * D_;
        const float* hp1 = hb + (long)(v1 ? tr1 : 0) * D_;
        float* o0 = out + (long)(b * T_ + (v0 ? tr0 : 0)) * (4 * D_);
        float* o1 = out + (long)(b * T_ + (v1 ? tr1 : 0)) * (4 * D_);
        if (nh == 0) {
            c2q_chunk<7>(0, dbase, a_s, u_s, rwhu_s, strip, g, tg, hp0, hp1, v0, v1, o0, o1);
            c2q_chunk<6>(7, dbase, a_s, u_s, rwhu_s, strip, g, tg, hp0, hp1, v0, v1, o0, o1);
        } else {
            c2q_chunk<7>(0, dbase, a_s, u_s, rwhu_s, strip, g, tg, hp0, hp1, v0, v1, o0, o1);
            c2q_chunk<5>(7, dbase, a_s, u_s, rwhu_s, strip, g, tg, hp0, hp1, v0, v1, o0, o1);
        }
    }

    // ---- chunk-local q2c partial ----
    __syncthreads();
    if (tid < D_) {
        const int RV = (T_ - t0 < TBLK) ? (T_ - t0) : TBLK;
        const float* hp = hb + (long)t0 * D_ + tid;
        float a0 = 0.f, a1 = 0.f, a2 = 0.f, a3 = 0.f;
        for (int r = 0; r < RV; r += 4) {
            a0 += es_s[r]     * hp[r * D_];
            a1 += es_s[r + 1] * hp[(r + 1) * D_];
            a2 += es_s[r + 2] * hp[(r + 2) * D_];
            a3 += es_s[r + 3] * hp[(r + 3) * D_];
        }
        g_part[(b * NBLK + c) * D_ + tid] = (a0 + a1) + (a2 + a3);
    }
}

// =====================================================================
// K2: per-batch combine -> g_q2c
// =====================================================================
__global__ __launch_bounds__(256) void bidaf_k2()
{
    __shared__ float ws[32];
    __shared__ float Ss;
    const int b = blockIdx.x, tid = threadIdx.x;
    if (tid < 32) {
        float2 cm = (tid < NBLK) ? g_cm[b * NBLK + tid] : make_float2(-3.0e38f, 0.f);
        float M = warpMax(cm.x);
        float e = (tid < NBLK) ? __expf(cm.x - M) : 0.f;
        float S = warpSum(e * cm.y);
        ws[tid] = e;
        if (tid == 0) Ss = S;
    }
    __syncthreads();
    if (tid < D_) {
        float acc = 0.f;
        #pragma unroll
        for (int c2 = 0; c2 < NBLK; c2++)
            acc += ws[c2] * g_part[(b * NBLK + c2) * D_ + tid];
        g_q2c[b * D_ + tid] = acc / Ss;
    }
}

// =====================================================================
// K3: out[b,t,600:800] = h * q2c
// =====================================================================
__global__ __launch_bounds__(256) void bidaf_k3(const float* __restrict__ h,
                                                float* __restrict__ out)
{
    long idx = (long)blockIdx.x * 256 + threadIdx.x;   // float4 index
    if (idx >= (long)B_ * T_ * 50) return;
    int d4 = (int)(idx % 50);
    long bt = idx / 50;
    int b = (int)(bt / T_);
    float4 hv = __ldg(((const float4*)h) + idx);
    float4 q  = __ldg(((const float4*)g_q2c) + b * 50 + d4);
    __stcs(((float4*)out) + bt * 200 + 150 + d4,
           make_float4(hv.x * q.x, hv.y * q.y, hv.z * q.z, hv.w * q.w));
}

// =====================================================================
extern "C" void kernel_launch(void* const* d_in, const int* in_sizes, int n_in,
                              void* d_out, int out_size)
{
    const float* h    = (const float*)d_in[0];
    const float* u    = (const float*)d_in[1];
    const float* w_h  = (const float*)d_in[2];
    const float* b_h  = (const float*)d_in[3];
    const float* w_u  = (const float*)d_in[4];
    const float* b_u  = (const float*)d_in[5];
    const float* w_hu = (const float*)d_in[6];
    const float* b_hu = (const float*)d_in[7];
    float* out = (float*)d_out;

    // u' + 2 stage buffers + su + rwhu + m + es
    constexpr int SMEM1 = (STG_OFF + 2 * STG + JP + D_ + JP + JP) * 4;  // 62432
    cudaFuncSetAttribute(bidaf_k1, cudaFuncAttributeMaxDynamicSharedMemorySize, SMEM1);

    bidaf_k1<<<dim3(NBLK, B_), TPB, SMEM1>>>(h, u, w_h, b_h, w_u, b_u, w_hu, b_hu, out);
    bidaf_k2<<<B_, 256>>>();
    int total4 = B_ * T_ * 50;
    bidaf_k3<<<(total4 + 255) / 256, 256>>>(h, out);
}